// round 9
// baseline (speedup 1.0000x reference)
#include <cuda_runtime.h>
#include <math.h>

// ---------------------------------------------------------------------------
// Problem constants
// ---------------------------------------------------------------------------
#define BB      64      // batch
#define FRAMES  100
#define FF      193     // feature rows (last one = period)
#define NSUB    4

// Packed weight offsets in g_WT (all transposed to (K, O): row k contiguous in o)
// GRUs are repacked: RZ = [Wih_rz ; Whh_rz] over [xg|s], IN = Wih_n, HN = Whh_n.
#define OFF_FW   0        // (388,64)  24832
#define OFF_FWG  24832    // (64,64)    4096
#define OFF_RZ1  28928    // (192,128) 24576
#define OFF_IN1  53504    // (128,64)   8192
#define OFF_HN1  61696    // (64,64)    4096
#define OFF_RZ2  65792
#define OFF_IN2  90368
#define OFF_HN2  98560
#define OFF_RZ3  102656
#define OFF_IN3  127232
#define OFF_HN3  135424
#define OFF_G1   139520   // (64,64)
#define OFF_G2   143616
#define OFF_G3   147712
#define OFF_SG   151808   // (128,128) 16384
#define OFF_SD   168192   // (320,128) 40960
#define OFF_OUT  209152   // (128,64)   8192
#define WT_TOTAL 217344

// ---------------------------------------------------------------------------
// Device scratch (allocation-free: __device__ globals)
// ---------------------------------------------------------------------------
__device__ __align__(16) float g_X [6400 * 256];
__device__ __align__(16) float g_H1[6400 * 256];
__device__ __align__(16) float g_H2[6400 * 256];
__device__ __align__(16) float g_C [6400 * 512];
__device__ __align__(16) float g_WT[WT_TOTAL];

// ---------------------------------------------------------------------------
// Activations: overflow-safe expf forms, no cancellation. Accurate under
// precise math; under fast-math they lower to short MUFU sequences with
// ~1e-6 rel error (safe: R8 margin was 6.4e-7 vs 1e-3 and the recurrence
// is contractive).
// ---------------------------------------------------------------------------
__device__ __forceinline__ float tanh_a(float x) {
    float t = fminf(fabsf(x), 15.0f);
    float e = expf(2.0f * t);            // in [1, e^30], finite
    float r = 1.0f - 2.0f / (e + 1.0f);  // tanh(t) >= 0, no cancellation
    return copysignf(r, x);
}

__device__ __forceinline__ float sig_a(float x) {
    float u = expf(-fabsf(x));           // (0, 1]
    return (x >= 0.0f) ? 1.0f / (1.0f + u) : u / (1.0f + u);
}

// ---------------------------------------------------------------------------
// Block-cooperative matvec:  y[o] = act( sum_k W[k*O + o] * x[k] ),  o < O
// W is (K, O) layout. 256 threads; thread owns 4 outputs and a k-residue
// class; partials reduced via smem. Coalesced float4 weight loads.
// ---------------------------------------------------------------------------
template<int O, int K, int ACT>
__device__ __forceinline__ void mv(const float* __restrict__ W,
                                   const float* __restrict__ x,
                                   float* __restrict__ y,
                                   float* __restrict__ redf,
                                   int tid)
{
    constexpr int G = O / 4;        // output groups of 4
    constexpr int P = 256 / G;      // k-split factor
    const int g = tid % G;
    const int p = tid / G;
    float4 acc = make_float4(0.f, 0.f, 0.f, 0.f);
    if (p < P) {
        #pragma unroll
        for (int k = p; k < K; k += P) {
            float4 w = *reinterpret_cast<const float4*>(W + k * O + 4 * g);
            float xv = x[k];
            acc.x = fmaf(w.x, xv, acc.x);
            acc.y = fmaf(w.y, xv, acc.y);
            acc.z = fmaf(w.z, xv, acc.z);
            acc.w = fmaf(w.w, xv, acc.w);
        }
        *reinterpret_cast<float4*>(redf + p * O + 4 * g) = acc;
    }
    __syncthreads();
    if (tid < O) {
        float s = 0.f;
        #pragma unroll
        for (int q = 0; q < P; ++q) s += redf[q * O + tid];
        y[tid] = ACT ? tanh_a(s) : s;
    }
    __syncthreads();
}

// ---------------------------------------------------------------------------
// Fused GRU stage: one load/FMA phase computes r/z sums (over [xg|s]), inew
// (over xg) and hnew (over s) concurrently on disjoint thread partitions,
// then one reduction computes all gates and updates s in place.
// Follows with the GLU: o = s * sigmoid(s @ Wg^T), written to skipslot and
// chained into xg[0:64].
// ---------------------------------------------------------------------------
__device__ __forceinline__ void gru_glu_fused(
    const float* __restrict__ WrzT,  // (192,128)
    const float* __restrict__ WinT,  // (128,64)
    const float* __restrict__ WhnT,  // (64,64)
    const float* __restrict__ WgT,   // (64,64)
    float* s, float* skipslot, float* xg,
    float* t64, float* redf, int tid)
{
    if (tid < 128) {
        // r/z sums: O=128, K=192 over xs=[xg(128)|s(64)]
        int g = tid & 31, p = tid >> 5;             // g:0..31, p:0..3
        float4 acc = make_float4(0.f, 0.f, 0.f, 0.f);
        #pragma unroll
        for (int k = p; k < 192; k += 4) {
            float4 w = *reinterpret_cast<const float4*>(WrzT + k * 128 + 4 * g);
            float xv = (k < 128) ? xg[k] : s[k - 128];
            acc.x = fmaf(w.x, xv, acc.x);
            acc.y = fmaf(w.y, xv, acc.y);
            acc.z = fmaf(w.z, xv, acc.z);
            acc.w = fmaf(w.w, xv, acc.w);
        }
        *reinterpret_cast<float4*>(redf + p * 128 + 4 * g) = acc;
    } else if (tid < 192) {
        // inew: O=64, K=128 over xg
        int t = tid - 128, g = t & 15, p = t >> 4;  // p:0..3
        float4 acc = make_float4(0.f, 0.f, 0.f, 0.f);
        #pragma unroll
        for (int k = p; k < 128; k += 4) {
            float4 w = *reinterpret_cast<const float4*>(WinT + k * 64 + 4 * g);
            float xv = xg[k];
            acc.x = fmaf(w.x, xv, acc.x);
            acc.y = fmaf(w.y, xv, acc.y);
            acc.z = fmaf(w.z, xv, acc.z);
            acc.w = fmaf(w.w, xv, acc.w);
        }
        *reinterpret_cast<float4*>(redf + 512 + p * 64 + 4 * g) = acc;
    } else {
        // hnew: O=64, K=64 over s
        int t = tid - 192, g = t & 15, p = t >> 4;
        float4 acc = make_float4(0.f, 0.f, 0.f, 0.f);
        #pragma unroll
        for (int k = p; k < 64; k += 4) {
            float4 w = *reinterpret_cast<const float4*>(WhnT + k * 64 + 4 * g);
            float xv = s[k];
            acc.x = fmaf(w.x, xv, acc.x);
            acc.y = fmaf(w.y, xv, acc.y);
            acc.z = fmaf(w.z, xv, acc.z);
            acc.w = fmaf(w.w, xv, acc.w);
        }
        *reinterpret_cast<float4*>(redf + 768 + p * 64 + 4 * g) = acc;
    }
    __syncthreads();
    if (tid < 64) {
        float rsum = 0.f, zsum = 0.f, isum = 0.f, hsum = 0.f;
        #pragma unroll
        for (int p = 0; p < 4; ++p) {
            rsum += redf[p * 128 + tid];
            zsum += redf[p * 128 + 64 + tid];
            isum += redf[512 + p * 64 + tid];
            hsum += redf[768 + p * 64 + tid];
        }
        float r = sig_a(rsum);
        float z = sig_a(zsum);
        float n = tanh_a(isum + r * hsum);
        s[tid] = (1.0f - z) * n + z * s[tid];
    }
    __syncthreads();
    mv<64, 64, 0>(WgT, s, t64, redf, tid);
    if (tid < 64) {
        float o = s[tid] * sig_a(t64[tid]);
        skipslot[tid] = o;
        xg[tid] = o;
    }
    __syncthreads();
}

// ---------------------------------------------------------------------------
// Prep kernels
// ---------------------------------------------------------------------------
__global__ void build_x_kernel(const float* __restrict__ features,
                               const float* __restrict__ gfeat)
{
    int r = blockIdx.x;            // r = b*FRAMES + t
    int tid = threadIdx.x;
    int b = r / FRAMES, t = r % FRAMES;
    float v;
    if (tid < 192) v = features[b * (FF * FRAMES) + tid * FRAMES + t];
    else           v = gfeat[b * 64 + (tid - 192)];
    g_X[r * 256 + tid] = v;
}

// Plain transposes for the 8 non-GRU matrices.
struct TPack { const float* src[8]; };

__global__ void transpose_all_kernel(TPack p)
{
    const int offs[8] = {OFF_FW, OFF_FWG, OFF_G1, OFF_G2, OFF_G3,
                         OFF_SG, OFF_SD, OFF_OUT};
    const int Os[8]   = {64, 64, 64, 64, 64, 128, 128, 64};
    const int Ks[8]   = {388, 64, 64, 64, 64, 128, 320, 128};
    int m = blockIdx.y;
    int i = blockIdx.x * 256 + threadIdx.x;
    int O = Os[m], K = Ks[m];
    if (i < O * K) {
        int o = i / K, kk = i % K;
        g_WT[offs[m] + kk * O + o] = p.src[m][i];
    }
}

// Repack GRU l: Wih (192x128 row-major), Whh (192x64) ->
//   RZ (192,128): rows k<128 from Wih[o,k] (o<128), rows k>=128 from Whh[o,k-128]
//   IN (128,64):  Wih[128+o, k];   HN (64,64): Whh[128+o, k]
struct GPack { const float* ih[3]; const float* hh[3]; };

__global__ void gru_pack_kernel(GPack p)
{
    const int base[3] = {OFF_RZ1, OFF_RZ2, OFF_RZ3};
    int l = blockIdx.y;
    const float* Wih = p.ih[l];
    const float* Whh = p.hh[l];
    int i = blockIdx.x * 256 + threadIdx.x;
    if (i < 24576) {                       // RZ
        int k = i >> 7, o = i & 127;
        float v = (k < 128) ? Wih[o * 128 + k] : Whh[o * 64 + (k - 128)];
        g_WT[base[l] + i] = v;
    } else if (i < 32768) {                // IN
        int j = i - 24576;
        int k = j >> 6, o = j & 63;
        g_WT[base[l] + i] = Wih[(128 + o) * 128 + k];
    } else if (i < 36864) {                // HN
        int j = i - 32768;
        int k = j >> 6, o = j & 63;
        g_WT[base[l] + 32768 + j] = Whh[(128 + o) * 64 + k];
    }
}

// Tiled GEMM with fused tanh: C[r,o] = tanh(sum_k A[r,k] * W[o,k]); K = 256.
__global__ void __launch_bounds__(256) gemm_tanh_kernel(
    const float* __restrict__ W, int mode)
{
    const float* A = (mode == 0) ? g_X : (mode == 1) ? g_H1 : g_H2;
    float* Cm      = (mode == 0) ? g_H1 : (mode == 1) ? g_H2 : g_C;
    const int K = 256;
    const int O = (mode == 2) ? 512 : 256;

    __shared__ __align__(16) float As[16][65];
    __shared__ __align__(16) float Ws[16][65];
    int tid = threadIdx.x;
    int tx = tid & 15, ty = tid >> 4;
    int r0 = blockIdx.x * 64, n0 = blockIdx.y * 64;
    int lm = tid >> 2, lk = (tid & 3) << 2;

    float acc[4][4];
    #pragma unroll
    for (int i = 0; i < 4; ++i)
        #pragma unroll
        for (int j = 0; j < 4; ++j) acc[i][j] = 0.f;

    for (int kk = 0; kk < K; kk += 16) {
        float4 a4 = *reinterpret_cast<const float4*>(A + (size_t)(r0 + lm) * K + kk + lk);
        float4 w4 = *reinterpret_cast<const float4*>(W + (size_t)(n0 + lm) * K + kk + lk);
        As[lk + 0][lm] = a4.x; As[lk + 1][lm] = a4.y;
        As[lk + 2][lm] = a4.z; As[lk + 3][lm] = a4.w;
        Ws[lk + 0][lm] = w4.x; Ws[lk + 1][lm] = w4.y;
        Ws[lk + 2][lm] = w4.z; Ws[lk + 3][lm] = w4.w;
        __syncthreads();
        #pragma unroll
        for (int kq = 0; kq < 16; ++kq) {
            float av[4], wv[4];
            #pragma unroll
            for (int i = 0; i < 4; ++i) av[i] = As[kq][ty * 4 + i];
            #pragma unroll
            for (int j = 0; j < 4; ++j) wv[j] = Ws[kq][tx * 4 + j];
            #pragma unroll
            for (int i = 0; i < 4; ++i)
                #pragma unroll
                for (int j = 0; j < 4; ++j)
                    acc[i][j] = fmaf(av[i], wv[j], acc[i][j]);
        }
        __syncthreads();
    }
    #pragma unroll
    for (int i = 0; i < 4; ++i)
        #pragma unroll
        for (int j = 0; j < 4; ++j)
            Cm[(size_t)(r0 + ty * 4 + i) * O + n0 + tx * 4 + j] = tanh_a(acc[i][j]);
}

// ---------------------------------------------------------------------------
// Persistent sequential sampler: one CTA per batch element, 400 serial steps.
// prev[i] == ring[(head + i) & 511]. Wsd/Wout/Wfw_g cached in 208 KB smem.
// ---------------------------------------------------------------------------
__global__ void __launch_bounds__(256, 1) seq_kernel(
    const float* __restrict__ features,
    const float* __restrict__ prev0,
    float* __restrict__ outg)
{
    extern __shared__ __align__(16) float dynsh[];
    float* WsdS  = dynsh;               // 40960 floats (160 KB)
    float* WoutS = dynsh + 40960;       //  8192 floats ( 32 KB)
    float* WfwgS = dynsh + 49152;       //  4096 floats ( 16 KB)

    __shared__ __align__(16) float ring[512];
    __shared__ __align__(16) float s1[64], s2[64], s3[64], sfw[128];
    __shared__ __align__(16) float xbuf[388];
    __shared__ __align__(16) float fwpre[64], t64[64], xg[128];
    __shared__ __align__(16) float skipb[320], sd[128], t128[128], so[128], outv[64];
    __shared__ __align__(16) float redf[1024];

    const int tid = threadIdx.x;
    const int b = blockIdx.x;

    for (int i = tid; i < 40960; i += 256) WsdS[i]  = g_WT[OFF_SD + i];
    for (int i = tid; i < 8192;  i += 256) WoutS[i] = g_WT[OFF_OUT + i];
    for (int i = tid; i < 4096;  i += 256) WfwgS[i] = g_WT[OFF_FWG + i];
    for (int i = tid; i < 512;   i += 256) ring[i]  = prev0[b * 512 + i];
    if (tid < 64)  { s1[tid] = 0.f; s2[tid] = 0.f; s3[tid] = 0.f; }
    if (tid < 128) sfw[tid] = 0.f;
    __syncthreads();

    int head = 0;
    for (int t = 0; t < FRAMES; ++t) {
        const int per = (int)rintf(features[b * (FF * FRAMES) + (FF - 1) * FRAMES + t]);
        const float* crow = g_C + (b * FRAMES + t) * 512;
        for (int k = 0; k < NSUB; ++k) {
            // -- build xbuf = [feat2s(128) | prev_sub(64) | lookback(68) | sfw(128)]
            if (tid < 128) {
                xbuf[tid]       = crow[tid * 4 + k];
                xbuf[260 + tid] = sfw[tid];
            } else if (tid < 192) {
                int i = tid - 128;
                xbuf[tid] = ring[(head + 448 + i) & 511];
            }
            if (tid >= 188) {                       // lookback j = 0..67
                int j = tid - 188;
                int idx = 512 - per + j - 2;
                if (idx >= 512) idx -= per;
                xbuf[192 + j] = ring[(head + idx) & 511];
            }
            if (tid >= 64 && tid < 128)             // skipb[256:320] = prev_sub
                skipb[192 + tid] = ring[(head + 448 + (tid - 64)) & 511];
            __syncthreads();

            // -- fw = glu(tanh(xbuf @ Wfw^T), Wfw_g)
            mv<64, 388, 1>(g_WT + OFF_FW, xbuf, fwpre, redf, tid);
            mv<64, 64, 0>(WfwgS, fwpre, t64, redf, tid);
            if (tid < 64) {
                float v = fwpre[tid] * sig_a(t64[tid]);
                skipb[192 + tid] = v;   // skip slot: fw
                xg[tid] = v;            // GRU1 input
            }
            if (tid >= 64 && tid < 128) xg[tid] = skipb[192 + tid]; // prev_sub
            __syncthreads();

            // -- 3 x fused (GRU + GLU)
            gru_glu_fused(g_WT + OFF_RZ1, g_WT + OFF_IN1, g_WT + OFF_HN1,
                          g_WT + OFF_G1, s1, skipb + 0,   xg, t64, redf, tid);
            gru_glu_fused(g_WT + OFF_RZ2, g_WT + OFF_IN2, g_WT + OFF_HN2,
                          g_WT + OFF_G2, s2, skipb + 64,  xg, t64, redf, tid);
            gru_glu_fused(g_WT + OFF_RZ3, g_WT + OFF_IN3, g_WT + OFF_HN3,
                          g_WT + OFF_G3, s3, skipb + 128, xg, t64, redf, tid);

            // -- skip decoder + output
            mv<128, 320, 1>(WsdS, skipb, sd, redf, tid);
            mv<128, 128, 0>(g_WT + OFF_SG, sd, t128, redf, tid);
            if (tid < 128) so[tid] = sd[tid] * sig_a(t128[tid]);
            __syncthreads();
            mv<64, 128, 1>(WoutS, so, outv, redf, tid);

            // -- emit, roll ring, update sfw state
            if (tid < 64) {
                float v = outv[tid];
                outg[b * 25600 + t * 256 + k * 64 + tid] = v;
                ring[(head + tid) & 511] = v;   // overwrites oldest 64
            }
            if (tid < 128) sfw[tid] = xbuf[tid];  // new sfw = current feat2s
            __syncthreads();
            head = (head + 64) & 511;
        }
    }
}

// ---------------------------------------------------------------------------
// Host launcher (graph-capturable: kernel launches only)
// ---------------------------------------------------------------------------
extern "C" void kernel_launch(void* const* d_in, const int* in_sizes, int n_in,
                              void* d_out, int out_size)
{
    const float* features = (const float*)d_in[0];
    const float* gfeat    = (const float*)d_in[1];
    const float* prev     = (const float*)d_in[2];
    const float* Wc1      = (const float*)d_in[3];
    const float* Wc2      = (const float*)d_in[4];
    const float* Wc3      = (const float*)d_in[5];
    float* out = (float*)d_out;

    build_x_kernel<<<6400, 256>>>(features, gfeat);

    TPack tp;
    tp.src[0] = (const float*)d_in[6];   // Wfw
    tp.src[1] = (const float*)d_in[7];   // Wfw_g
    tp.src[2] = (const float*)d_in[14];  // Wg1
    tp.src[3] = (const float*)d_in[15];  // Wg2
    tp.src[4] = (const float*)d_in[16];  // Wg3
    tp.src[5] = (const float*)d_in[17];  // Wsg
    tp.src[6] = (const float*)d_in[18];  // Wsd
    tp.src[7] = (const float*)d_in[19];  // Wout
    transpose_all_kernel<<<dim3(161, 8), 256>>>(tp);

    GPack gp;
    gp.ih[0] = (const float*)d_in[8];  gp.hh[0] = (const float*)d_in[9];
    gp.ih[1] = (const float*)d_in[10]; gp.hh[1] = (const float*)d_in[11];
    gp.ih[2] = (const float*)d_in[12]; gp.hh[2] = (const float*)d_in[13];
    gru_pack_kernel<<<dim3(144, 3), 256>>>(gp);

    gemm_tanh_kernel<<<dim3(100, 4), 256>>>(Wc1, 0);
    gemm_tanh_kernel<<<dim3(100, 4), 256>>>(Wc2, 1);
    gemm_tanh_kernel<<<dim3(100, 8), 256>>>(Wc3, 2);

    cudaFuncSetAttribute(seq_kernel,
                         cudaFuncAttributeMaxDynamicSharedMemorySize, 212992);
    seq_kernel<<<BB, 256, 212992>>>(features, prev, out);
}

// round 11
// speedup vs baseline: 2.3092x; 2.3092x over previous
#include <cuda_runtime.h>
#include <math.h>

// ---------------------------------------------------------------------------
// Problem constants
// ---------------------------------------------------------------------------
#define BB      64      // batch
#define FRAMES  100
#define FF      193     // feature rows (last one = period)
#define NSUB    4

// Packed transposed-weight offsets (layout (K, O), row k contiguous in o)
#define OFF_FW   0        // (388,64)   24832
#define OFF_FWG  24832    // (64,64)    4096
#define OFF_IH1  28928    // (128,192)  24576
#define OFF_HH1  53504    // (64,192)   12288
#define OFF_IH2  65792
#define OFF_HH2  90368
#define OFF_IH3  102656
#define OFF_HH3  127232
#define OFF_G1   139520   // (64,64)
#define OFF_G2   143616
#define OFF_G3   147712
#define OFF_SG   151808   // (128,128)  16384
#define OFF_SD   168192   // (320,128)  40960
#define OFF_OUT  209152   // (128,64)   8192
#define WT_TOTAL 217344

// ---------------------------------------------------------------------------
// Device scratch (allocation-free: __device__ globals)
// ---------------------------------------------------------------------------
__device__ __align__(16) float g_X [6400 * 256];
__device__ __align__(16) float g_H1[6400 * 256];
__device__ __align__(16) float g_H2[6400 * 256];
__device__ __align__(16) float g_C [6400 * 512];
__device__ __align__(16) float g_WT[WT_TOTAL];

// ---------------------------------------------------------------------------
// Accurate activations (expm1f is not fast-math-substituted; no cancellation).
// Known-good from R8 (rel_err 6.4e-7).
// ---------------------------------------------------------------------------
__device__ __forceinline__ float tanh_acc(float x) {
    float t  = fabsf(x);
    float em = expm1f(-2.0f * t);        // in (-1, 0]
    float r  = -em / (2.0f + em);        // tanh(t)
    return copysignf(r, x);
}

__device__ __forceinline__ float sig_acc(float x) {
    if (x >= 0.0f) {
        float em = expm1f(-x);
        return 1.0f / (2.0f + em);
    } else {
        float em = expm1f(x);
        return (1.0f + em) / (2.0f + em);
    }
}

// ---------------------------------------------------------------------------
// Dual-batch block-cooperative matvec: for nb in {0,1}:
//   y_nb[o] = act( sum_k W[k*O + o] * x_nb[k] )
// Each weight float4 is loaded ONCE and applied to both batches -> halves the
// L2 weight stream vs one-batch-per-CTA. 256 threads.
// R10 bugfix: reduction covers all 2*O outputs via a strided loop (for O=192,
// 2*O=384 > 256 threads; the old `if (tid < 2*O)` left batch1 outputs
// 64..191 unwritten -> rel_err 1.59).
// ---------------------------------------------------------------------------
template<int O, int K, int ACT>
__device__ __forceinline__ void mv2(const float* __restrict__ W,
                                    const float* __restrict__ x0,
                                    const float* __restrict__ x1,
                                    float* __restrict__ y0,
                                    float* __restrict__ y1,
                                    float* __restrict__ redf,
                                    int tid)
{
    constexpr int G = O / 4;        // output groups of 4
    constexpr int P = 256 / G;      // k-split factor
    const int g = tid % G;
    const int p = tid / G;
    float4 a0 = make_float4(0.f, 0.f, 0.f, 0.f);
    float4 a1 = make_float4(0.f, 0.f, 0.f, 0.f);
    if (p < P) {
        #pragma unroll
        for (int k = p; k < K; k += P) {
            float4 w = *reinterpret_cast<const float4*>(W + k * O + 4 * g);
            float v0 = x0[k], v1 = x1[k];
            a0.x = fmaf(w.x, v0, a0.x); a1.x = fmaf(w.x, v1, a1.x);
            a0.y = fmaf(w.y, v0, a0.y); a1.y = fmaf(w.y, v1, a1.y);
            a0.z = fmaf(w.z, v0, a0.z); a1.z = fmaf(w.z, v1, a1.z);
            a0.w = fmaf(w.w, v0, a0.w); a1.w = fmaf(w.w, v1, a1.w);
        }
        *reinterpret_cast<float4*>(redf + p * O + 4 * g)        = a0;
        *reinterpret_cast<float4*>(redf + 1024 + p * O + 4 * g) = a1;
    }
    __syncthreads();
    #pragma unroll
    for (int u = tid; u < 2 * O; u += 256) {
        int nb = (u >= O) ? 1 : 0;
        int i  = u - nb * O;
        const float* rb = redf + nb * 1024;
        float s = 0.f;
        #pragma unroll
        for (int q = 0; q < P; ++q) s += rb[q * O + i];
        float r = ACT ? tanh_acc(s) : s;
        if (nb) y1[i] = r; else y0[i] = r;
    }
    __syncthreads();
}

// ---------------------------------------------------------------------------
// Prep kernels (identical to R8)
// ---------------------------------------------------------------------------
__global__ void build_x_kernel(const float* __restrict__ features,
                               const float* __restrict__ gfeat)
{
    int r = blockIdx.x;            // r = b*FRAMES + t
    int tid = threadIdx.x;
    int b = r / FRAMES, t = r % FRAMES;
    float v;
    if (tid < 192) v = features[b * (FF * FRAMES) + tid * FRAMES + t];
    else           v = gfeat[b * 64 + (tid - 192)];
    g_X[r * 256 + tid] = v;
}

struct TPack { const float* src[14]; };

__global__ void transpose_all_kernel(TPack p)
{
    const int offs[14] = {OFF_FW, OFF_FWG, OFF_IH1, OFF_HH1, OFF_IH2, OFF_HH2,
                          OFF_IH3, OFF_HH3, OFF_G1, OFF_G2, OFF_G3, OFF_SG,
                          OFF_SD, OFF_OUT};
    const int Os[14]   = {64, 64, 192, 192, 192, 192, 192, 192,
                          64, 64, 64, 128, 128, 64};
    const int Ks[14]   = {388, 64, 128, 64, 128, 64, 128, 64,
                          64, 64, 64, 128, 320, 128};
    int m = blockIdx.y;
    int i = blockIdx.x * 256 + threadIdx.x;
    int O = Os[m], K = Ks[m];
    if (i < O * K) {
        int o = i / K, kk = i % K;
        g_WT[offs[m] + kk * O + o] = p.src[m][i];
    }
}

// Tiled GEMM with fused tanh: C[r,o] = tanh(sum_k A[r,k] * W[o,k]); K = 256.
__global__ void __launch_bounds__(256) gemm_tanh_kernel(
    const float* __restrict__ W, int mode)
{
    const float* A = (mode == 0) ? g_X : (mode == 1) ? g_H1 : g_H2;
    float* Cm      = (mode == 0) ? g_H1 : (mode == 1) ? g_H2 : g_C;
    const int K = 256;
    const int O = (mode == 2) ? 512 : 256;

    __shared__ __align__(16) float As[16][65];
    __shared__ __align__(16) float Ws[16][65];
    int tid = threadIdx.x;
    int tx = tid & 15, ty = tid >> 4;
    int r0 = blockIdx.x * 64, n0 = blockIdx.y * 64;
    int lm = tid >> 2, lk = (tid & 3) << 2;

    float acc[4][4];
    #pragma unroll
    for (int i = 0; i < 4; ++i)
        #pragma unroll
        for (int j = 0; j < 4; ++j) acc[i][j] = 0.f;

    for (int kk = 0; kk < K; kk += 16) {
        float4 a4 = *reinterpret_cast<const float4*>(A + (size_t)(r0 + lm) * K + kk + lk);
        float4 w4 = *reinterpret_cast<const float4*>(W + (size_t)(n0 + lm) * K + kk + lk);
        As[lk + 0][lm] = a4.x; As[lk + 1][lm] = a4.y;
        As[lk + 2][lm] = a4.z; As[lk + 3][lm] = a4.w;
        Ws[lk + 0][lm] = w4.x; Ws[lk + 1][lm] = w4.y;
        Ws[lk + 2][lm] = w4.z; Ws[lk + 3][lm] = w4.w;
        __syncthreads();
        #pragma unroll
        for (int kq = 0; kq < 16; ++kq) {
            float av[4], wv[4];
            #pragma unroll
            for (int i = 0; i < 4; ++i) av[i] = As[kq][ty * 4 + i];
            #pragma unroll
            for (int j = 0; j < 4; ++j) wv[j] = Ws[kq][tx * 4 + j];
            #pragma unroll
            for (int i = 0; i < 4; ++i)
                #pragma unroll
                for (int j = 0; j < 4; ++j)
                    acc[i][j] = fmaf(av[i], wv[j], acc[i][j]);
        }
        __syncthreads();
    }
    #pragma unroll
    for (int i = 0; i < 4; ++i)
        #pragma unroll
        for (int j = 0; j < 4; ++j)
            Cm[(size_t)(r0 + ty * 4 + i) * O + n0 + tx * 4 + j] = tanh_acc(acc[i][j]);
}

// ---------------------------------------------------------------------------
// Persistent sequential sampler: TWO batch elements per CTA (32 CTAs),
// 400 serial steps. Weight loads amortized across both batches.
// prev[nb][i] == ring[nb][(head + i) & 511].
// ---------------------------------------------------------------------------
__global__ void __launch_bounds__(256, 1) seq_kernel(
    const float* __restrict__ features,
    const float* __restrict__ prev0,
    float* __restrict__ outg)
{
    extern __shared__ __align__(16) float dynsh[];
    float* WsdS  = dynsh;               // 40960 floats (160 KB)
    float* WoutS = dynsh + 40960;       //  8192 floats ( 32 KB)

    __shared__ __align__(16) float ring[2][512];
    __shared__ __align__(16) float s1[2][64], s2[2][64], s3[2][64], sfw[2][128];
    __shared__ __align__(16) float xbuf[2][388];
    __shared__ __align__(16) float fwpre[2][64], t64[2][64], xg[2][128];
    __shared__ __align__(16) float gi[2][192], gh[2][192];
    __shared__ __align__(16) float skipb[2][320], sd[2][128], t128[2][128];
    __shared__ __align__(16) float so[2][128], outv[2][64];
    __shared__ __align__(16) float redf[2048];

    const int tid = threadIdx.x;
    const int b0 = blockIdx.x * 2;

    for (int i = tid; i < 40960; i += 256) WsdS[i]  = g_WT[OFF_SD + i];
    for (int i = tid; i < 8192;  i += 256) WoutS[i] = g_WT[OFF_OUT + i];
    for (int i = tid; i < 1024;  i += 256)
        ring[i >> 9][i & 511] = prev0[(b0 + (i >> 9)) * 512 + (i & 511)];
    if (tid < 128) {
        int nb = tid >> 6, i = tid & 63;
        s1[nb][i] = 0.f; s2[nb][i] = 0.f; s3[nb][i] = 0.f;
    }
    {
        int nb = tid >> 7, i = tid & 127;
        sfw[nb][i] = 0.f;
    }
    __syncthreads();

    int head = 0;
    for (int t = 0; t < FRAMES; ++t) {
        const int per0 = (int)rintf(features[(b0    ) * (FF * FRAMES) + (FF - 1) * FRAMES + t]);
        const int per1 = (int)rintf(features[(b0 + 1) * (FF * FRAMES) + (FF - 1) * FRAMES + t]);
        const float* crow0 = g_C + ((b0    ) * FRAMES + t) * 512;
        const float* crow1 = g_C + ((b0 + 1) * FRAMES + t) * 512;
        for (int k = 0; k < NSUB; ++k) {
            // -- build xbuf = [feat2s(128)|prev_sub(64)|lookback(68)|sfw(128)]
            {   // feat2s + sfw: 256 tasks
                int nb = tid >> 7, i = tid & 127;
                const float* crow = nb ? crow1 : crow0;
                xbuf[nb][i]       = crow[i * 4 + k];
                xbuf[nb][260 + i] = sfw[nb][i];
            }
            if (tid < 128) {   // prev_sub (also feeds skipb slot 4)
                int nb = tid >> 6, i = tid & 63;
                float v = ring[nb][(head + 448 + i) & 511];
                xbuf[nb][128 + i]  = v;
                skipb[nb][256 + i] = v;
            }
            if (tid >= 120) {  // lookback: 136 tasks on tids 120..255
                int q = tid - 120;                // 0..135
                int nb = (q >= 68) ? 1 : 0;
                int j  = q - nb * 68;             // 0..67
                int p  = nb ? per1 : per0;
                int idx = 512 - p + j - 2;
                if (idx >= 512) idx -= p;
                xbuf[nb][192 + j] = ring[nb][(head + idx) & 511];
            }
            __syncthreads();

            // -- fw = glu(tanh(xbuf @ Wfw^T), Wfw_g)
            mv2<64, 388, 1>(g_WT + OFF_FW, xbuf[0], xbuf[1],
                            fwpre[0], fwpre[1], redf, tid);
            mv2<64, 64, 0>(g_WT + OFF_FWG, fwpre[0], fwpre[1],
                           t64[0], t64[1], redf, tid);
            if (tid < 128) {
                int nb = tid >> 6, i = tid & 63;
                float v = fwpre[nb][i] * sig_acc(t64[nb][i]);
                skipb[nb][192 + i] = v;            // skip slot: fw
                xg[nb][i] = v;                     // GRU1 input
            } else {
                int nb = (tid - 128) >> 6, i = (tid - 128) & 63;
                xg[nb][64 + i] = skipb[nb][256 + i];   // prev_sub half
            }
            __syncthreads();

            // -- 3 x (GRU + GLU), R8 structure vectorized over 2 batches
            #pragma unroll
            for (int l = 0; l < 3; ++l) {
                const float* WihT = g_WT + (l == 0 ? OFF_IH1 : l == 1 ? OFF_IH2 : OFF_IH3);
                const float* WhhT = g_WT + (l == 0 ? OFF_HH1 : l == 1 ? OFF_HH2 : OFF_HH3);
                const float* WgT  = g_WT + (l == 0 ? OFF_G1  : l == 1 ? OFF_G2  : OFF_G3);
                float* sa0 = (l == 0 ? s1[0] : l == 1 ? s2[0] : s3[0]);
                float* sa1 = (l == 0 ? s1[1] : l == 1 ? s2[1] : s3[1]);

                mv2<192, 128, 0>(WihT, xg[0], xg[1], gi[0], gi[1], redf, tid);
                mv2<192, 64, 0>(WhhT, sa0, sa1, gh[0], gh[1], redf, tid);
                if (tid < 128) {
                    int nb = tid >> 6, i = tid & 63;
                    float* sa = nb ? sa1 : sa0;
                    float r = sig_acc(gi[nb][i]        + gh[nb][i]);
                    float z = sig_acc(gi[nb][64 + i]   + gh[nb][64 + i]);
                    float n = tanh_acc(gi[nb][128 + i] + r * gh[nb][128 + i]);
                    sa[i] = (1.0f - z) * n + z * sa[i];
                }
                __syncthreads();
                mv2<64, 64, 0>(WgT, sa0, sa1, t64[0], t64[1], redf, tid);
                if (tid < 128) {
                    int nb = tid >> 6, i = tid & 63;
                    float* sa = nb ? sa1 : sa0;
                    float o = sa[i] * sig_acc(t64[nb][i]);
                    skipb[nb][l * 64 + i] = o;
                    xg[nb][i] = o;
                }
                __syncthreads();
            }

            // -- skip decoder + output
            mv2<128, 320, 1>(WsdS, skipb[0], skipb[1], sd[0], sd[1], redf, tid);
            mv2<128, 128, 0>(g_WT + OFF_SG, sd[0], sd[1], t128[0], t128[1], redf, tid);
            {
                int nb = tid >> 7, i = tid & 127;
                so[nb][i] = sd[nb][i] * sig_acc(t128[nb][i]);
            }
            __syncthreads();
            mv2<64, 128, 1>(WoutS, so[0], so[1], outv[0], outv[1], redf, tid);

            // -- emit, roll ring, update sfw state
            if (tid < 128) {
                int nb = tid >> 6, i = tid & 63;
                float v = outv[nb][i];
                outg[(b0 + nb) * 25600 + t * 256 + k * 64 + i] = v;
                ring[nb][(head + i) & 511] = v;    // overwrites oldest 64
            }
            {
                int nb = tid >> 7, i = tid & 127;
                sfw[nb][i] = xbuf[nb][i];          // new sfw = current feat2s
            }
            __syncthreads();
            head = (head + 64) & 511;
        }
    }
}

// ---------------------------------------------------------------------------
// Host launcher (graph-capturable: kernel launches only)
// ---------------------------------------------------------------------------
extern "C" void kernel_launch(void* const* d_in, const int* in_sizes, int n_in,
                              void* d_out, int out_size)
{
    const float* features = (const float*)d_in[0];
    const float* gfeat    = (const float*)d_in[1];
    const float* prev     = (const float*)d_in[2];
    const float* Wc1      = (const float*)d_in[3];
    const float* Wc2      = (const float*)d_in[4];
    const float* Wc3      = (const float*)d_in[5];
    float* out = (float*)d_out;

    build_x_kernel<<<6400, 256>>>(features, gfeat);

    TPack tp;
    for (int i = 0; i < 14; ++i) tp.src[i] = (const float*)d_in[6 + i];
    transpose_all_kernel<<<dim3(160, 14), 256>>>(tp);

    gemm_tanh_kernel<<<dim3(100, 4), 256>>>(Wc1, 0);
    gemm_tanh_kernel<<<dim3(100, 4), 256>>>(Wc2, 1);
    gemm_tanh_kernel<<<dim3(100, 8), 256>>>(Wc3, 2);

    cudaFuncSetAttribute(seq_kernel,
                         cudaFuncAttributeMaxDynamicSharedMemorySize, 196608);
    seq_kernel<<<BB / 2, 256, 196608>>>(features, prev, out);
}

// round 12
// speedup vs baseline: 2.5221x; 1.0922x over previous
#include <cuda_runtime.h>
#include <math.h>

// ---------------------------------------------------------------------------
// Problem constants
// ---------------------------------------------------------------------------
#define BB      64      // batch
#define FRAMES  100
#define FF      193     // feature rows (last one = period)
#define NSUB    4
#define NT      512     // seq_kernel threads

// Packed transposed-weight offsets (layout (K, O), row k contiguous in o)
#define OFF_FW   0        // (388,64)   24832
#define OFF_FWG  24832    // (64,64)    4096
#define OFF_IH1  28928    // (128,192)  24576
#define OFF_HH1  53504    // (64,192)   12288
#define OFF_IH2  65792
#define OFF_HH2  90368
#define OFF_IH3  102656
#define OFF_HH3  127232
#define OFF_G1   139520   // (64,64)
#define OFF_G2   143616
#define OFF_G3   147712
#define OFF_SG   151808   // (128,128)  16384
#define OFF_SD   168192   // (320,128)  40960
#define OFF_OUT  209152   // (128,64)   8192
#define WT_TOTAL 217344

// ---------------------------------------------------------------------------
// Device scratch (allocation-free: __device__ globals)
// ---------------------------------------------------------------------------
__device__ __align__(16) float g_X [6400 * 256];
__device__ __align__(16) float g_H1[6400 * 256];
__device__ __align__(16) float g_H2[6400 * 256];
__device__ __align__(16) float g_C [6400 * 512];
__device__ __align__(16) float g_WT[WT_TOTAL];

// ---------------------------------------------------------------------------
// Accurate activations (expm1f is not fast-math-substituted; no cancellation).
// Known-good since R8 (rel_err 6.4e-7).
// ---------------------------------------------------------------------------
__device__ __forceinline__ float tanh_acc(float x) {
    float t  = fabsf(x);
    float em = expm1f(-2.0f * t);        // in (-1, 0]
    float r  = -em / (2.0f + em);        // tanh(t)
    return copysignf(r, x);
}

__device__ __forceinline__ float sig_acc(float x) {
    if (x >= 0.0f) {
        float em = expm1f(-x);
        return 1.0f / (2.0f + em);
    } else {
        float em = expm1f(x);
        return (1.0f + em) / (2.0f + em);
    }
}

// ---------------------------------------------------------------------------
// Block-cooperative matvec (NT=512 threads): y[o] = act(sum_k W[k*O+o]*x[k]).
// W is (K, O) layout. Thread owns 4 outputs and a k-residue class; partials
// reduced via smem (redf: up to 2048 floats). Doubling P vs the 256-thread
// version halves each thread's load/FMA chain -> less exposed latency at
// 4 warps/SMSP.
// ---------------------------------------------------------------------------
template<int O, int K, int ACT>
__device__ __forceinline__ void mv(const float* __restrict__ W,
                                   const float* __restrict__ x,
                                   float* __restrict__ y,
                                   float* __restrict__ redf,
                                   int tid)
{
    constexpr int G = O / 4;        // output groups of 4
    constexpr int P = NT / G;       // k-split factor (32 / 16 / 10)
    const int g = tid % G;
    const int p = tid / G;
    float4 acc = make_float4(0.f, 0.f, 0.f, 0.f);
    if (p < P) {
        #pragma unroll
        for (int k = p; k < K; k += P) {
            float4 w = *reinterpret_cast<const float4*>(W + k * O + 4 * g);
            float xv = x[k];
            acc.x = fmaf(w.x, xv, acc.x);
            acc.y = fmaf(w.y, xv, acc.y);
            acc.z = fmaf(w.z, xv, acc.z);
            acc.w = fmaf(w.w, xv, acc.w);
        }
        *reinterpret_cast<float4*>(redf + p * O + 4 * g) = acc;
    }
    __syncthreads();
    if (tid < O) {
        float s = 0.f;
        #pragma unroll
        for (int q = 0; q < P; ++q) s += redf[q * O + tid];
        y[tid] = ACT ? tanh_acc(s) : s;
    }
    __syncthreads();
}

// GRU + GLU stage (R8 structure). xg = [input(64) | prev_sub(64)], s updated
// in place; GLU result to skipslot and chained into xg[0:64].
__device__ __forceinline__ void gru_glu(const float* WihT, const float* WhhT,
                                        const float* WgT,
                                        float* s, float* skipslot, float* xg,
                                        float* gi, float* gh, float* t64,
                                        float* redf, int tid)
{
    mv<192, 128, 0>(WihT, xg, gi, redf, tid);
    mv<192, 64, 0>(WhhT, s, gh, redf, tid);
    if (tid < 64) {
        float r = sig_acc(gi[tid]        + gh[tid]);
        float z = sig_acc(gi[64 + tid]   + gh[64 + tid]);
        float n = tanh_acc(gi[128 + tid] + r * gh[128 + tid]);
        s[tid] = (1.0f - z) * n + z * s[tid];
    }
    __syncthreads();
    mv<64, 64, 0>(WgT, s, t64, redf, tid);
    if (tid < 64) {
        float o = s[tid] * sig_acc(t64[tid]);
        skipslot[tid] = o;
        xg[tid] = o;
    }
    __syncthreads();
}

// ---------------------------------------------------------------------------
// Prep kernels (identical to R8)
// ---------------------------------------------------------------------------
__global__ void build_x_kernel(const float* __restrict__ features,
                               const float* __restrict__ gfeat)
{
    int r = blockIdx.x;            // r = b*FRAMES + t
    int tid = threadIdx.x;
    int b = r / FRAMES, t = r % FRAMES;
    float v;
    if (tid < 192) v = features[b * (FF * FRAMES) + tid * FRAMES + t];
    else           v = gfeat[b * 64 + (tid - 192)];
    g_X[r * 256 + tid] = v;
}

struct TPack { const float* src[14]; };

__global__ void transpose_all_kernel(TPack p)
{
    const int offs[14] = {OFF_FW, OFF_FWG, OFF_IH1, OFF_HH1, OFF_IH2, OFF_HH2,
                          OFF_IH3, OFF_HH3, OFF_G1, OFF_G2, OFF_G3, OFF_SG,
                          OFF_SD, OFF_OUT};
    const int Os[14]   = {64, 64, 192, 192, 192, 192, 192, 192,
                          64, 64, 64, 128, 128, 64};
    const int Ks[14]   = {388, 64, 128, 64, 128, 64, 128, 64,
                          64, 64, 64, 128, 320, 128};
    int m = blockIdx.y;
    int i = blockIdx.x * 256 + threadIdx.x;
    int O = Os[m], K = Ks[m];
    if (i < O * K) {
        int o = i / K, kk = i % K;
        g_WT[offs[m] + kk * O + o] = p.src[m][i];
    }
}

// Tiled GEMM with fused tanh: C[r,o] = tanh(sum_k A[r,k] * W[o,k]); K = 256.
__global__ void __launch_bounds__(256) gemm_tanh_kernel(
    const float* __restrict__ W, int mode)
{
    const float* A = (mode == 0) ? g_X : (mode == 1) ? g_H1 : g_H2;
    float* Cm      = (mode == 0) ? g_H1 : (mode == 1) ? g_H2 : g_C;
    const int K = 256;
    const int O = (mode == 2) ? 512 : 256;

    __shared__ __align__(16) float As[16][65];
    __shared__ __align__(16) float Ws[16][65];
    int tid = threadIdx.x;
    int tx = tid & 15, ty = tid >> 4;
    int r0 = blockIdx.x * 64, n0 = blockIdx.y * 64;
    int lm = tid >> 2, lk = (tid & 3) << 2;

    float acc[4][4];
    #pragma unroll
    for (int i = 0; i < 4; ++i)
        #pragma unroll
        for (int j = 0; j < 4; ++j) acc[i][j] = 0.f;

    for (int kk = 0; kk < K; kk += 16) {
        float4 a4 = *reinterpret_cast<const float4*>(A + (size_t)(r0 + lm) * K + kk + lk);
        float4 w4 = *reinterpret_cast<const float4*>(W + (size_t)(n0 + lm) * K + kk + lk);
        As[lk + 0][lm] = a4.x; As[lk + 1][lm] = a4.y;
        As[lk + 2][lm] = a4.z; As[lk + 3][lm] = a4.w;
        Ws[lk + 0][lm] = w4.x; Ws[lk + 1][lm] = w4.y;
        Ws[lk + 2][lm] = w4.z; Ws[lk + 3][lm] = w4.w;
        __syncthreads();
        #pragma unroll
        for (int kq = 0; kq < 16; ++kq) {
            float av[4], wv[4];
            #pragma unroll
            for (int i = 0; i < 4; ++i) av[i] = As[kq][ty * 4 + i];
            #pragma unroll
            for (int j = 0; j < 4; ++j) wv[j] = Ws[kq][tx * 4 + j];
            #pragma unroll
            for (int i = 0; i < 4; ++i)
                #pragma unroll
                for (int j = 0; j < 4; ++j)
                    acc[i][j] = fmaf(av[i], wv[j], acc[i][j]);
        }
        __syncthreads();
    }
    #pragma unroll
    for (int i = 0; i < 4; ++i)
        #pragma unroll
        for (int j = 0; j < 4; ++j)
            Cm[(size_t)(r0 + ty * 4 + i) * O + n0 + tx * 4 + j] = tanh_acc(acc[i][j]);
}

// ---------------------------------------------------------------------------
// Persistent sequential sampler: one CTA per batch element (64 CTAs),
// NT=512 threads, 400 serial steps. prev[i] == ring[(head + i) & 511].
// Wsd + Wout cached in 192 KB dynamic smem.
// ---------------------------------------------------------------------------
__global__ void __launch_bounds__(NT, 1) seq_kernel(
    const float* __restrict__ features,
    const float* __restrict__ prev0,
    float* __restrict__ outg)
{
    extern __shared__ __align__(16) float dynsh[];
    float* WsdS  = dynsh;               // 40960 floats (160 KB)
    float* WoutS = dynsh + 40960;       //  8192 floats ( 32 KB)

    __shared__ __align__(16) float ring[512];
    __shared__ __align__(16) float s1[64], s2[64], s3[64], sfw[128];
    __shared__ __align__(16) float xbuf[388];
    __shared__ __align__(16) float fwpre[64], t64[64], xg[128];
    __shared__ __align__(16) float gi[192], gh[192];
    __shared__ __align__(16) float skipb[320], sd[128], t128[128], so[128], outv[64];
    __shared__ __align__(16) float redf[2048];

    const int tid = threadIdx.x;
    const int b = blockIdx.x;

    for (int i = tid; i < 40960; i += NT) WsdS[i]  = g_WT[OFF_SD + i];
    for (int i = tid; i < 8192;  i += NT) WoutS[i] = g_WT[OFF_OUT + i];
    for (int i = tid; i < 512;   i += NT) ring[i]  = prev0[b * 512 + i];
    if (tid < 64)  { s1[tid] = 0.f; s2[tid] = 0.f; s3[tid] = 0.f; }
    if (tid < 128) sfw[tid] = 0.f;
    __syncthreads();

    int head = 0;
    for (int t = 0; t < FRAMES; ++t) {
        const int per = (int)rintf(features[b * (FF * FRAMES) + (FF - 1) * FRAMES + t]);
        const float* crow = g_C + (b * FRAMES + t) * 512;
        for (int k = 0; k < NSUB; ++k) {
            // -- build xbuf = [feat2s(128) | prev_sub(64) | lookback(68) | sfw(128)]
            if (tid < 128) {
                xbuf[tid]       = crow[tid * 4 + k];
                xbuf[260 + tid] = sfw[tid];
            } else if (tid < 192) {
                int i = tid - 128;
                xbuf[tid] = ring[(head + 448 + i) & 511];
            }
            if (tid >= 188 && tid < 256) {          // lookback j = 0..67
                int j = tid - 188;
                int idx = 512 - per + j - 2;
                if (idx >= 512) idx -= per;
                xbuf[192 + j] = ring[(head + idx) & 511];
            }
            if (tid >= 256 && tid < 320)            // skipb[256:320] = prev_sub
                skipb[tid] = ring[(head + 448 + (tid - 256)) & 511];
            __syncthreads();

            // -- fw = glu(tanh(xbuf @ Wfw^T), Wfw_g)
            mv<64, 388, 1>(g_WT + OFF_FW, xbuf, fwpre, redf, tid);
            mv<64, 64, 0>(g_WT + OFF_FWG, fwpre, t64, redf, tid);
            if (tid < 64) {
                float v = fwpre[tid] * sig_acc(t64[tid]);
                skipb[192 + tid] = v;   // skip slot: fw
                xg[tid] = v;            // GRU1 input
            }
            if (tid >= 64 && tid < 128) xg[tid] = skipb[192 + tid]; // prev_sub
            __syncthreads();

            // -- 3 x (GRU + GLU)
            gru_glu(g_WT + OFF_IH1, g_WT + OFF_HH1, g_WT + OFF_G1,
                    s1, skipb + 0,   xg, gi, gh, t64, redf, tid);
            gru_glu(g_WT + OFF_IH2, g_WT + OFF_HH2, g_WT + OFF_G2,
                    s2, skipb + 64,  xg, gi, gh, t64, redf, tid);
            gru_glu(g_WT + OFF_IH3, g_WT + OFF_HH3, g_WT + OFF_G3,
                    s3, skipb + 128, xg, gi, gh, t64, redf, tid);

            // -- skip decoder + output
            mv<128, 320, 1>(WsdS, skipb, sd, redf, tid);
            mv<128, 128, 0>(g_WT + OFF_SG, sd, t128, redf, tid);
            if (tid < 128) so[tid] = sd[tid] * sig_acc(t128[tid]);
            __syncthreads();
            mv<64, 128, 1>(WoutS, so, outv, redf, tid);

            // -- emit, roll ring, update sfw state
            if (tid < 64) {
                float v = outv[tid];
                outg[b * 25600 + t * 256 + k * 64 + tid] = v;
                ring[(head + tid) & 511] = v;   // overwrites oldest 64
            }
            if (tid < 128) sfw[tid] = xbuf[tid];  // new sfw = current feat2s
            __syncthreads();
            head = (head + 64) & 511;
        }
    }
}

// ---------------------------------------------------------------------------
// Host launcher (graph-capturable: kernel launches only)
// ---------------------------------------------------------------------------
extern "C" void kernel_launch(void* const* d_in, const int* in_sizes, int n_in,
                              void* d_out, int out_size)
{
    const float* features = (const float*)d_in[0];
    const float* gfeat    = (const float*)d_in[1];
    const float* prev     = (const float*)d_in[2];
    const float* Wc1      = (const float*)d_in[3];
    const float* Wc2      = (const float*)d_in[4];
    const float* Wc3      = (const float*)d_in[5];
    float* out = (float*)d_out;

    build_x_kernel<<<6400, 256>>>(features, gfeat);

    TPack tp;
    for (int i = 0; i < 14; ++i) tp.src[i] = (const float*)d_in[6 + i];
    transpose_all_kernel<<<dim3(160, 14), 256>>>(tp);

    gemm_tanh_kernel<<<dim3(100, 4), 256>>>(Wc1, 0);
    gemm_tanh_kernel<<<dim3(100, 4), 256>>>(Wc2, 1);
    gemm_tanh_kernel<<<dim3(100, 8), 256>>>(Wc3, 2);

    cudaFuncSetAttribute(seq_kernel,
                         cudaFuncAttributeMaxDynamicSharedMemorySize, 196608);
    seq_kernel<<<BB, NT, 196608>>>(features, prev, out);
}